// round 16
// baseline (speedup 1.0000x reference)
#include <cuda_runtime.h>
#include <cuda_fp16.h>
#include <math.h>
#include <stdint.h>

#define NB 4
#define HW 2500
#define CIN 512
#define COUT 512
#define KDIM 4608
#define NANCH 22500
#define NPRE 3000
#define NPOST 300
#define NCHUNK 6
#define CHUNK 4096
#define PADN (NCHUNK*CHUNK)

#define OFF_LOCS 0
#define OFF_SCORES (NB*NANCH*4)
#define OFF_ROIS (OFF_SCORES+NB*NANCH*2)
#define OFF_RIDX (OFF_ROIS+NB*NPOST*4)
#define OFF_ANCH (OFF_RIDX+NB*NPOST)

#define WPAD 56
#define PLANE 3072
#define KC 64
#define NKC_HALF 36
#define NTILES_N 22
#define BUFB 65536u
#define CONV_SMEM (2*65536)
#define XSCALE 256.0f
#define WSCALE 64.0f
#define UNSCALE (1.0f/16384.0f)
#define HEADS_SMEM (128*33*16)

// ---------------- scratch ----------------
__device__ __align__(16) __half g_xh[2][3][(size_t)NB*CIN*PLANE];
__device__ __align__(16) __half g_wh[2][(size_t)COUT*KDIM];
__device__ float g_feat2[2][(size_t)NB*HW*COUT];
__device__ float g_boxes[NB*NANCH*4];
__device__ unsigned char g_valid[NB*NANCH];
__device__ unsigned long long g_keys[NB*PADN];
__device__ float g_sboxes[NB*NPRE*4];
__device__ unsigned char g_svalid[NB*NPRE];
__device__ unsigned g_sup[NB][3008][96];

// ---------------- PTX helpers ----------------
__device__ __forceinline__ uint32_t smem_u32(const void* p) {
    uint32_t a;
    asm("{ .reg .u64 t; cvta.to.shared.u64 t, %1; cvt.u32.u64 %0, t; }" : "=r"(a) : "l"(p));
    return a;
}
__device__ __forceinline__ void cp16(uint32_t dst, const void* src) {
    asm volatile("cp.async.cg.shared.global [%0], [%1], 16;" :: "r"(dst), "l"(src) : "memory");
}
#define CP_COMMIT() asm volatile("cp.async.commit_group;" ::: "memory")
#define CP_WAIT(n)  asm volatile("cp.async.wait_group %0;" :: "n"(n) : "memory")

__device__ __forceinline__ void ldsm4(uint32_t* r, uint32_t a) {
    asm volatile("ldmatrix.sync.aligned.m8n8.x4.shared.b16 {%0,%1,%2,%3}, [%4];"
        : "=r"(r[0]), "=r"(r[1]), "=r"(r[2]), "=r"(r[3]) : "r"(a));
}
__device__ __forceinline__ void ldsm4t(uint32_t* r, uint32_t a) {
    asm volatile("ldmatrix.sync.aligned.m8n8.x4.trans.shared.b16 {%0,%1,%2,%3}, [%4];"
        : "=r"(r[0]), "=r"(r[1]), "=r"(r[2]), "=r"(r[3]) : "r"(a));
}
__device__ __forceinline__ void mma16816(float* c, const uint32_t* a, const uint32_t* b) {
    asm volatile("mma.sync.aligned.m16n8k16.row.col.f32.f16.f16.f32 "
        "{%0,%1,%2,%3}, {%4,%5,%6,%7}, {%8,%9}, {%0,%1,%2,%3};"
        : "+f"(c[0]), "+f"(c[1]), "+f"(c[2]), "+f"(c[3])
        : "r"(a[0]), "r"(a[1]), "r"(a[2]), "r"(a[3]), "r"(b[0]), "r"(b[1]));
}

// ---------------- splits (scaled 2-term fp16) ----------------
__global__ void split_x_kernel(const float* __restrict__ X) {
    const int bc = blockIdx.x;
    const float* src = X + (size_t)bc * HW;
    for (int idx = threadIdx.x; idx < PLANE; idx += 256) {
        int yy = idx / WPAD, xx = idx - yy * WPAD;
        int iy = yy - 1;
#pragma unroll
        for (int kx = 0; kx < 3; kx++) {
            int ix = xx + kx - 1;
            float v = 0.f;
            if (iy >= 0 && iy < 50 && ix >= 0 && ix < 50) v = src[iy * 50 + ix];
            v *= XSCALE;
            __half h0 = __float2half(v);
            __half h1 = __float2half(v - __half2float(h0));
            size_t o = (size_t)bc * PLANE + idx;
            g_xh[0][kx][o] = h0; g_xh[1][kx][o] = h1;
        }
    }
}
__global__ void split_w_kernel(const float* __restrict__ W) {
    int i4 = blockIdx.x * 256 + threadIdx.x;
    if (i4 >= COUT * KDIM / 4) return;
    float4 v = ((const float4*)W)[i4];
    float e[4] = {v.x, v.y, v.z, v.w};
#pragma unroll
    for (int q = 0; q < 4; q++) {
        float vv = e[q] * WSCALE;
        __half h0 = __float2half(vv);
        g_wh[0][i4 * 4 + q] = h0;
        g_wh[1][i4 * 4 + q] = __float2half(vv - __half2float(h0));
    }
}

// ---------------- conv: 512 threads, 16 warps (4m x 4n), warp tile 32x32 -------
__global__ __launch_bounds__(512, 1)
void conv_mma_kernel() {
    extern __shared__ char dsm[];
    const uint32_t sbase = smem_u32(dsm);
    const int tid = threadIdx.x;
    const int lane = tid & 31, warp = tid >> 5;
    const int p0 = blockIdx.x * 128;
    const int m0 = blockIdx.y * 128;
    const int b  = blockIdx.z >> 1;
    const int kh = blockIdx.z & 1;
    const int kbase = kh * NKC_HALF;
    const int warp_m = (warp >> 2) * 32;
    const int warp_n = (warp & 3) * 32;

    float C[2][4][4];
    float S[2][4][4];
#pragma unroll
    for (int i = 0; i < 2; i++)
#pragma unroll
        for (int j = 0; j < 4; j++)
#pragma unroll
            for (int r = 0; r < 4; r++) { C[i][j][r] = 0.f; S[i][j][r] = 0.f; }

    const int m_lane = lane & 15, hi = lane >> 4;
    const int nb = warp_n >> 3;

    auto load_stage = [&](int kc, uint32_t base) {
        const int k0 = kc * KC;
#pragma unroll
        for (int s = 0; s < 2; s++) {
            const __half* wsrc = g_wh[s];
#pragma unroll
            for (int it = 0; it < 2; it++) {      // A: 128 rows x 8 chunks
                int idx = tid + it * 512;
                int m = idx >> 3, c = idx & 7;
                cp16(base + (uint32_t)s * 16384u + (uint32_t)m * 128u + (uint32_t)((c ^ (m & 7)) << 4),
                     wsrc + (size_t)(m0 + m) * KDIM + k0 + c * 8);
            }
#pragma unroll
            for (int it = 0; it < 2; it++) {      // B: 64 k x 16 chunks
                int idx = tid + it * 512;
                int k = idx >> 4, c = idx & 15;
                int kk = k0 + k;
                int cin = kk / 9, rem = kk - cin * 9;
                int ky = rem / 3, kx = rem - ky * 3;
                const __half* src = &g_xh[s][kx][(size_t)(b * CIN + cin) * PLANE + ky * WPAD + p0 + c * 8];
                cp16(base + 32768u + (uint32_t)s * 16384u + (uint32_t)k * 256u + (uint32_t)((c ^ (k & 7)) << 4), src);
            }
        }
        CP_COMMIT();
    };

    load_stage(kbase, sbase);

    for (int lc = 0; lc < NKC_HALF; lc++) {
        CP_WAIT(0);
        __syncthreads();
        if (lc + 1 < NKC_HALF)
            load_stage(kbase + lc + 1, sbase + (uint32_t)((lc + 1) & 1) * BUFB);

        const uint32_t cur = sbase + (uint32_t)(lc & 1) * BUFB;
        const uint32_t sA0 = cur, sA1 = cur + 16384u;
        const uint32_t sB0 = cur + 32768u, sB1 = cur + 49152u;
#pragma unroll
        for (int ks = 0; ks < 4; ks++) {
            uint32_t a0f[2][4], a1f[2][4], b0f[2][4], b1f[2][4];
#pragma unroll
            for (int mi = 0; mi < 2; mi++) {
                int m = warp_m + mi * 16 + m_lane;
                uint32_t off = (uint32_t)m * 128u + (uint32_t)(((ks * 2 + hi) ^ (m_lane & 7)) << 4);
                ldsm4(a0f[mi], sA0 + off);
                ldsm4(a1f[mi], sA1 + off);
            }
#pragma unroll
            for (int ni = 0; ni < 2; ni++) {
                int k = ks * 16 + m_lane;
                uint32_t off = (uint32_t)k * 256u + (uint32_t)(((nb + ni * 2 + hi) ^ (m_lane & 7)) << 4);
                ldsm4t(b0f[ni], sB0 + off);
                ldsm4t(b1f[ni], sB1 + off);
            }
#pragma unroll
            for (int mi = 0; mi < 2; mi++)
#pragma unroll
                for (int g = 0; g < 4; g++) {
                    float* cc = C[mi][g];
                    const uint32_t* pb0 = &b0f[g >> 1][(g & 1) * 2];
                    const uint32_t* pb1 = &b1f[g >> 1][(g & 1) * 2];
                    mma16816(cc, a0f[mi], pb0);
                    mma16816(cc, a0f[mi], pb1);
                    mma16816(cc, a1f[mi], pb0);
                }
        }
        if ((lc & 1) || lc == NKC_HALF - 1) {
#pragma unroll
            for (int mi = 0; mi < 2; mi++)
#pragma unroll
                for (int g = 0; g < 4; g++)
#pragma unroll
                    for (int r = 0; r < 4; r++) {
                        S[mi][g][r] += C[mi][g][r];
                        C[mi][g][r] = 0.f;
                    }
        }
    }

    float* dstp = g_feat2[kh];
#pragma unroll
    for (int mi = 0; mi < 2; mi++)
#pragma unroll
        for (int g = 0; g < 4; g++)
#pragma unroll
            for (int r = 0; r < 4; r++) {
                int pp = p0 + warp_n + g * 8 + (lane & 3) * 2 + (r & 1);
                int y = pp / WPAD, x = pp - y * WPAD;
                if (x < 50 && y < 50) {
                    int m = m0 + warp_m + mi * 16 + (lane >> 2) + 8 * (r >> 1);
                    dstp[((size_t)(b * HW + y * 50 + x) << 9) + m] = S[mi][g][r] * UNSCALE;
                }
            }
}

// ---------------- anchors (also writes pad keys) ----------------
__device__ __forceinline__ void anchor_of(int i, float& ax1, float& ay1, float& ax2, float& ay2) {
    int p = i / 9, a = i - p * 9;
    int y = p / 50, x = p - y * 50;
    int ri = a / 3, si = a - ri * 3;
    const double ratios[3] = {0.5, 1.0, 2.0};
    const double scales[3] = {8.0, 16.0, 32.0};
    double hh = 16.0 * scales[si] * sqrt(ratios[ri]);
    double ww = 16.0 * scales[si] * sqrt(1.0 / ratios[ri]);
    float sx = (float)(x * 16), sy = (float)(y * 16);
    ax1 = sx + (float)(8.0 - ww / 2.0); ay1 = sy + (float)(8.0 - hh / 2.0);
    ax2 = sx + (float)(8.0 + ww / 2.0); ay2 = sy + (float)(8.0 + hh / 2.0);
}
__global__ void anchor_kernel(float* __restrict__ out) {
    int i = blockIdx.x * blockDim.x + threadIdx.x;
    if (i < NANCH) {
        float a1, b1, a2, b2;
        anchor_of(i, a1, b1, a2, b2);
        out[OFF_ANCH + i * 4 + 0] = a1; out[OFF_ANCH + i * 4 + 1] = b1;
        out[OFF_ANCH + i * 4 + 2] = a2; out[OFF_ANCH + i * 4 + 3] = b2;
    } else if (i < PADN) {
#pragma unroll
        for (int b = 0; b < NB; b++)
            g_keys[(size_t)b * PADN + i] = 0xFFFFFFFFFFFFFFFFull;
    }
}

// ---------------- 1x1 heads v2 + fused decode ----------------
__device__ __forceinline__ float dim_to_float(const int* p) {
    int v = *p;
    if (v > 0 && v < 100000) return (float)v;
    return __int_as_float(v);
}

__global__ __launch_bounds__(256)
void heads_kernel(const float* __restrict__ cbias,
                  const float* __restrict__ lw, const float* __restrict__ lb,
                  const float* __restrict__ sw, const float* __restrict__ sb,
                  const int* __restrict__ imh, const int* __restrict__ imw,
                  float* __restrict__ out) {
    extern __shared__ float4 ft4[];
    __shared__ float vals[54][36];
    const int b = blockIdx.y, p0 = blockIdx.x * 32, tid = threadIdx.x;
    const int lane = tid & 31, warp = tid >> 5;

    for (int idx = tid; idx < 32 * 128; idx += 256) {
        int px = idx >> 7, cq = idx & 127;
        float4 v = make_float4(0.f, 0.f, 0.f, 0.f);
        if (p0 + px < HW) {
            size_t o = ((size_t)(b * HW + p0 + px) << 9) + cq * 4;
            float4 vA = *(const float4*)&g_feat2[0][o];
            float4 vB = *(const float4*)&g_feat2[1][o];
            float4 bz = ((const float4*)cbias)[cq];
            v.x = fmaxf(vA.x + vB.x + bz.x, 0.f);
            v.y = fmaxf(vA.y + vB.y + bz.y, 0.f);
            v.z = fmaxf(vA.z + vB.z + bz.z, 0.f);
            v.w = fmaxf(vA.w + vB.w + bz.w, 0.f);
        }
        ft4[cq * 33 + px] = v;
    }
    __syncthreads();

    const int o0 = warp * 7;
    const float4* wrow[7];
    float bias7[7];
#pragma unroll
    for (int oi = 0; oi < 7; oi++) {
        int o = o0 + oi;
        if (o < 36)      { wrow[oi] = (const float4*)(lw + (o << 9));        bias7[oi] = lb[o]; }
        else if (o < 54) { wrow[oi] = (const float4*)(sw + ((o - 36) << 9)); bias7[oi] = sb[o - 36]; }
        else             { wrow[oi] = (const float4*)lw;                     bias7[oi] = 0.f; }
    }

    float acc[7] = {0.f, 0.f, 0.f, 0.f, 0.f, 0.f, 0.f};
#pragma unroll 4
    for (int cq = 0; cq < 128; cq++) {
        float4 f = ft4[cq * 33 + lane];
#pragma unroll
        for (int oi = 0; oi < 7; oi++) {
            float4 wv = __ldg(wrow[oi] + cq);
            acc[oi] += wv.x * f.x + wv.y * f.y + wv.z * f.z + wv.w * f.w;
        }
    }

    const int p = p0 + lane;
#pragma unroll
    for (int oi = 0; oi < 7; oi++) {
        int o = o0 + oi;
        if (o >= 54) break;
        float s = acc[oi] + bias7[oi];
        vals[o][lane] = s;
        if (p < HW) {
            if (o < 36) {
                int a = o >> 2, j = o & 3;
                out[OFF_LOCS + b * (NANCH * 4) + (p * 9 + a) * 4 + j] = s;
            } else {
                int oo = o - 36, a = oo >> 1, j = oo & 1;
                out[OFF_SCORES + b * (NANCH * 2) + (p * 9 + a) * 2 + j] = s;
            }
        }
    }
    __syncthreads();

    const float Wf = dim_to_float(imw), Hf = dim_to_float(imh);
    for (int t = tid; t < 32 * 9; t += 256) {
        int px = t / 9, a = t - px * 9;
        int pp = p0 + px;
        if (pp >= HW) continue;
        int i = pp * 9 + a;
        float ax1, ay1, ax2, ay2;
        anchor_of(i, ax1, ay1, ax2, ay2);
        float l0 = vals[a * 4 + 0][px], l1 = vals[a * 4 + 1][px];
        float l2 = vals[a * 4 + 2][px], l3 = vals[a * 4 + 3][px];
        float aw = ax2 - ax1, ah = ay2 - ay1;
        float cx = l0 * aw + ax1 + 0.5f * aw;
        float cy = l1 * ah + ay1 + 0.5f * ah;
        float ww = expf(l2) * aw, hh = expf(l3) * ah;
        float x1 = fminf(fmaxf(cx - 0.5f * ww, 0.f), Wf);
        float y1 = fminf(fmaxf(cy - 0.5f * hh, 0.f), Hf);
        float x2 = fminf(fmaxf(cx + 0.5f * ww, 0.f), Wf);
        float y2 = fminf(fmaxf(cy + 0.5f * hh, 0.f), Hf);
        bool valid = (x2 - x1 + 1.f >= 16.f) && (y2 - y1 + 1.f >= 16.f);
        float* bx = &g_boxes[((size_t)b * NANCH + i) * 4];
        bx[0] = x1; bx[1] = y1; bx[2] = x2; bx[3] = y2;
        g_valid[b * NANCH + i] = valid ? 1 : 0;
        float s0 = vals[36 + a * 2][px], s1 = vals[37 + a * 2][px];
        float m = fmaxf(s0, s1);
        float e0 = expf(s0 - m), e1 = expf(s1 - m);
        float fg = e1 / (e0 + e1);
        float score = valid ? fg : __int_as_float(0xFF800000);
        unsigned u = __float_as_uint(score);
        unsigned sbits = (u & 0x80000000u) ? ~u : (u | 0x80000000u);
        g_keys[(size_t)b * PADN + i] = ((unsigned long long)(~sbits) << 32) | (unsigned)i;
    }
}

// ---------------- per-chunk bitonic sort ----------------
__global__ __launch_bounds__(512)
void sort_kernel() {
    __shared__ unsigned long long sk[CHUNK];
    const int c = blockIdx.x % NCHUNK, b = blockIdx.x / NCHUNK;
    unsigned long long* gk = g_keys + (size_t)b * PADN + c * CHUNK;
    for (int i = threadIdx.x; i < CHUNK; i += 512) sk[i] = gk[i];
    __syncthreads();
    for (int k = 2; k <= CHUNK; k <<= 1)
        for (int j = k >> 1; j > 0; j >>= 1) {
            for (int t = threadIdx.x; t < CHUNK; t += 512) {
                int l = t ^ j;
                if (l > t) {
                    bool up = ((t & k) == 0);
                    unsigned long long a = sk[t], bv = sk[l];
                    if ((a > bv) == up) { sk[t] = bv; sk[l] = a; }
                }
            }
            __syncthreads();
        }
    for (int i = threadIdx.x; i < CHUNK; i += 512) gk[i] = sk[i];
}

// ---------------- co-rank merge -> exact top-3000 ----------------
__global__ void merge_kernel() {
    const int b = blockIdx.y;
    const int t = blockIdx.x * blockDim.x + threadIdx.x;
    if (t >= NCHUNK * NPRE) return;
    const int c = t / NPRE, i = t - c * NPRE;
    const unsigned long long* base = g_keys + (size_t)b * PADN;
    unsigned long long key = base[c * CHUNK + i];
    if ((unsigned)(key >> 32) == 0xFFFFFFFFu) return;
    int rank = i;
#pragma unroll
    for (int cc = 0; cc < NCHUNK; cc++) {
        if (cc == c) continue;
        const unsigned long long* arr = base + cc * CHUNK;
        int pos = 0;
#pragma unroll
        for (int s = CHUNK / 2; s > 0; s >>= 1)
            if (arr[pos + s - 1] < key) pos += s;
        rank += pos;
    }
    if (rank < NPRE) {
        int idx = (int)(key & 0xFFFFFFFFull);
        int o = b * NPRE + rank;
        ((float4*)g_sboxes)[o] = *(const float4*)&g_boxes[((size_t)b * NANCH + idx) * 4];
        g_svalid[o] = g_valid[b * NANCH + idx];
    }
}

// ---------------- NMS: suppression bitmatrix (upper-triangle words only) --------
__global__ __launch_bounds__(1024)
void nms_build_kernel() {
    __shared__ float4 bx[NPRE];
    const int b = blockIdx.y, tid = threadIdx.x;
    const int lane = tid & 31, warp = tid >> 5;
    for (int idx = tid; idx < NPRE; idx += 1024)
        bx[idx] = ((const float4*)g_sboxes)[b * NPRE + idx];
    __syncthreads();
    int i = blockIdx.x * 32 + warp;
    if (i >= NPRE) return;
    float4 bi = bx[i];
    float ai = (bi.z - bi.x) * (bi.w - bi.y);
    const int w_start = i >> 5;
    for (int jw = w_start; jw < 94; jw++) {
        int j = jw * 32 + lane;
        bool sup = false;
        if (j < NPRE && j > i) {
            float4 bj = bx[j];
            float iw = fmaxf(fminf(bi.z, bj.z) - fmaxf(bi.x, bj.x), 0.f);
            float ih = fmaxf(fminf(bi.w, bj.w) - fmaxf(bi.y, bj.y), 0.f);
            float inter = iw * ih;
            float aj = (bj.z - bj.x) * (bj.w - bj.y);
            sup = inter / (ai + aj - inter + 1e-9f) > 0.7f;
        }
        unsigned word = __ballot_sync(0xFFFFFFFFu, sup);
        if (lane == 0) g_sup[b][i][jw] = word;
    }
    if (lane < 2) g_sup[b][i][94 + lane] = 0;
}

// ---------------- NMS: single-warp greedy scan (early exit @300 kept) ----------
#define STILE 64
__global__ __launch_bounds__(256)
void nms_scan_kernel(float* __restrict__ out) {
    extern __shared__ unsigned srows[];
    __shared__ unsigned keepw[96];
    __shared__ int done_flag;
    const int b = blockIdx.x, tid = threadIdx.x;
    const int lane = tid & 31, warp = tid >> 5;

    if (tid == 0) done_flag = 0;
    for (int w = tid; w < 96; w += 256) {
        unsigned word = 0;
        for (int q = 0; q < 32; q++) {
            int idx = w * 32 + q;
            if (idx < NPRE && g_svalid[b * NPRE + idx]) word |= (1u << q);
        }
        keepw[w] = word;
    }
    for (int idx = tid; idx < STILE * 24; idx += 256) {
        int i = idx / 24, w4 = idx % 24;
        uint4 v = make_uint4(0, 0, 0, 0);
        if (i < NPRE) v = ((const uint4*)g_sup[b][i])[w4];
        ((uint4*)srows)[idx] = v;
    }
    __syncthreads();

    int cnt_kept = 0;
    const int ntiles = (NPRE + STILE - 1) / STILE;
    for (int t = 0; t < ntiles; t++) {
        if (warp > 0 && t + 1 < ntiles) {
            unsigned* buf = srows + ((t + 1) & 1) * STILE * 96;
            for (int idx = tid - 32; idx < STILE * 24; idx += 224) {
                int i = (t + 1) * STILE + idx / 24, w4 = idx % 24;
                uint4 v = make_uint4(0, 0, 0, 0);
                if (i < NPRE) v = ((const uint4*)g_sup[b][i])[w4];
                ((uint4*)buf)[idx] = v;
            }
        }
        if (warp == 0) {
            const unsigned* buf = srows + (t & 1) * STILE * 96;
            unsigned wcur = 0;
            for (int ii = 0; ii < STILE; ii++) {
                int i = t * STILE + ii;
                if (i >= NPRE) break;
                int cw = i >> 5, bit = i & 31;
                if (bit == 0) { __syncwarp(); wcur = keepw[cw]; }
                if ((wcur >> bit) & 1) {
                    const unsigned* row = buf + ii * 96;
                    wcur &= ~row[cw];
                    keepw[lane]      &= ~row[lane];
                    keepw[lane + 32] &= ~row[lane + 32];
                    keepw[lane + 64] &= ~row[lane + 64];
                    if (++cnt_kept >= NPOST) break;
                }
            }
            __syncwarp();
            if (lane == 0 && cnt_kept >= NPOST) done_flag = 1;
        }
        __syncthreads();
        if (done_flag) break;
    }

    for (int q = tid; q < NPOST * 4; q += 256) out[OFF_ROIS + b * (NPOST * 4) + q] = 0.f;
    for (int q = tid; q < NPOST; q += 256) out[OFF_RIDX + b * NPOST + q] = (float)b;
    __syncthreads();

    if (warp == 0) {
        int cnt = 0;
        for (int w0 = 0; w0 < 94; w0++) {
            unsigned flags = keepw[w0];
            int j = w0 * 32 + lane;
            bool f = (flags >> lane) & 1;
            int pos = cnt + __popc(flags & ((1u << lane) - 1u));
            if (f && pos < NPOST && j < NPRE) {
                float4 bb = ((const float4*)g_sboxes)[b * NPRE + j];
                float* o = out + OFF_ROIS + b * (NPOST * 4) + pos * 4;
                o[0] = bb.x; o[1] = bb.y; o[2] = bb.z; o[3] = bb.w;
            }
            cnt += __popc(flags);
            if (cnt >= NPOST) break;
        }
    }
}

// ---------------- launcher ----------------
extern "C" void kernel_launch(void* const* d_in, const int* in_sizes, int n_in,
                              void* d_out, int out_size) {
    const float* x  = (const float*)d_in[0];
    const float* w1 = (const float*)d_in[1];
    const float* b1 = (const float*)d_in[2];
    const float* lw = (const float*)d_in[3];
    const float* lb = (const float*)d_in[4];
    const float* sw = (const float*)d_in[5];
    const float* sb = (const float*)d_in[6];
    const int* ih   = (const int*)d_in[7];
    const int* iw   = (const int*)d_in[8];
    float* out = (float*)d_out;

    cudaFuncSetAttribute(conv_mma_kernel, cudaFuncAttributeMaxDynamicSharedMemorySize, CONV_SMEM);
    cudaFuncSetAttribute(heads_kernel, cudaFuncAttributeMaxDynamicSharedMemorySize, HEADS_SMEM);
    cudaFuncSetAttribute(nms_scan_kernel, cudaFuncAttributeMaxDynamicSharedMemorySize, 2 * STILE * 96 * 4);

    anchor_kernel<<<(PADN + 255) / 256, 256>>>(out);                        // launch 0
    split_x_kernel<<<NB * CIN, 256>>>(x);                                   // launch 1
    split_w_kernel<<<(COUT * KDIM / 4 + 255) / 256, 256>>>(w1);             // launch 2
    conv_mma_kernel<<<dim3(NTILES_N, 4, NB * 2), 512, CONV_SMEM>>>();       // launch 3 (profiled)
    heads_kernel<<<dim3((HW + 31) / 32, NB), 256, HEADS_SMEM>>>(b1, lw, lb, sw, sb, ih, iw, out);
    sort_kernel<<<NB * NCHUNK, 512>>>();
    merge_kernel<<<dim3((NCHUNK * NPRE + 255) / 256, NB), 256>>>();
    nms_build_kernel<<<dim3((NPRE + 31) / 32, NB), 1024>>>();
    nms_scan_kernel<<<NB, 256, 2 * STILE * 96 * 4>>>(out);
}

// round 17
// speedup vs baseline: 1.0351x; 1.0351x over previous
#include <cuda_runtime.h>
#include <cuda_fp16.h>
#include <math.h>
#include <stdint.h>

#define NB 4
#define HW 2500
#define CIN 512
#define COUT 512
#define KDIM 4608
#define NANCH 22500
#define NPRE 3000
#define NPOST 300
#define NCHUNK 6
#define CHUNK 4096
#define PADN (NCHUNK*CHUNK)

#define OFF_LOCS 0
#define OFF_SCORES (NB*NANCH*4)
#define OFF_ROIS (OFF_SCORES+NB*NANCH*2)
#define OFF_RIDX (OFF_ROIS+NB*NPOST*4)
#define OFF_ANCH (OFF_RIDX+NB*NPOST)

#define WPAD 56
#define PLANE 3072
#define KC 64
#define NKC_HALF 36
#define NTILES_N 22
#define BUFB 65536u
#define CONV_SMEM (2*65536)
#define XSCALE 256.0f
#define WSCALE 64.0f
#define UNSCALE (1.0f/16384.0f)
#define HEADS_SMEM (128*33*16)

// ---------------- scratch ----------------
__device__ __align__(16) __half g_xh[2][3][(size_t)NB*CIN*PLANE];
__device__ __align__(16) __half g_wh[2][(size_t)COUT*KDIM];
__device__ float g_feat2[2][(size_t)NB*HW*COUT];
__device__ float g_boxes[NB*NANCH*4];
__device__ unsigned char g_valid[NB*NANCH];
__device__ unsigned long long g_keys[NB*PADN];
__device__ float g_sboxes[NB*NPRE*4];
__device__ unsigned char g_svalid[NB*NPRE];
__device__ unsigned g_sup[NB][3008][96];

// ---------------- PTX helpers ----------------
__device__ __forceinline__ uint32_t smem_u32(const void* p) {
    uint32_t a;
    asm("{ .reg .u64 t; cvta.to.shared.u64 t, %1; cvt.u32.u64 %0, t; }" : "=r"(a) : "l"(p));
    return a;
}
__device__ __forceinline__ void cp16(uint32_t dst, const void* src) {
    asm volatile("cp.async.cg.shared.global [%0], [%1], 16;" :: "r"(dst), "l"(src) : "memory");
}
#define CP_COMMIT() asm volatile("cp.async.commit_group;" ::: "memory")
#define CP_WAIT(n)  asm volatile("cp.async.wait_group %0;" :: "n"(n) : "memory")

__device__ __forceinline__ void ldsm4(uint32_t* r, uint32_t a) {
    asm volatile("ldmatrix.sync.aligned.m8n8.x4.shared.b16 {%0,%1,%2,%3}, [%4];"
        : "=r"(r[0]), "=r"(r[1]), "=r"(r[2]), "=r"(r[3]) : "r"(a));
}
__device__ __forceinline__ void ldsm4t(uint32_t* r, uint32_t a) {
    asm volatile("ldmatrix.sync.aligned.m8n8.x4.trans.shared.b16 {%0,%1,%2,%3}, [%4];"
        : "=r"(r[0]), "=r"(r[1]), "=r"(r[2]), "=r"(r[3]) : "r"(a));
}
__device__ __forceinline__ void mma16816(float* c, const uint32_t* a, const uint32_t* b) {
    asm volatile("mma.sync.aligned.m16n8k16.row.col.f32.f16.f16.f32 "
        "{%0,%1,%2,%3}, {%4,%5,%6,%7}, {%8,%9}, {%0,%1,%2,%3};"
        : "+f"(c[0]), "+f"(c[1]), "+f"(c[2]), "+f"(c[3])
        : "r"(a[0]), "r"(a[1]), "r"(a[2]), "r"(a[3]), "r"(b[0]), "r"(b[1]));
}

// ---------------- splits (scaled 2-term fp16) ----------------
__global__ void split_x_kernel(const float* __restrict__ X) {
    const int bc = blockIdx.x;
    const float* src = X + (size_t)bc * HW;
    for (int idx = threadIdx.x; idx < PLANE; idx += 256) {
        int yy = idx / WPAD, xx = idx - yy * WPAD;
        int iy = yy - 1;
#pragma unroll
        for (int kx = 0; kx < 3; kx++) {
            int ix = xx + kx - 1;
            float v = 0.f;
            if (iy >= 0 && iy < 50 && ix >= 0 && ix < 50) v = src[iy * 50 + ix];
            v *= XSCALE;
            __half h0 = __float2half(v);
            __half h1 = __float2half(v - __half2float(h0));
            size_t o = (size_t)bc * PLANE + idx;
            g_xh[0][kx][o] = h0; g_xh[1][kx][o] = h1;
        }
    }
}
__global__ void split_w_kernel(const float* __restrict__ W) {
    int i4 = blockIdx.x * 256 + threadIdx.x;
    if (i4 >= COUT * KDIM / 4) return;
    float4 v = ((const float4*)W)[i4];
    float e[4] = {v.x, v.y, v.z, v.w};
#pragma unroll
    for (int q = 0; q < 4; q++) {
        float vv = e[q] * WSCALE;
        __half h0 = __float2half(vv);
        g_wh[0][i4 * 4 + q] = h0;
        g_wh[1][i4 * 4 + q] = __float2half(vv - __half2float(h0));
    }
}

// ---------------- conv (R12 optimum): 256 thr, 128x128 tile, K-split ----------
__global__ __launch_bounds__(256, 1)
void conv_mma_kernel() {
    extern __shared__ char dsm[];
    const uint32_t sbase = smem_u32(dsm);
    const int tid = threadIdx.x;
    const int lane = tid & 31, warp = tid >> 5;
    const int p0 = blockIdx.x * 128;
    const int m0 = blockIdx.y * 128;
    const int b  = blockIdx.z >> 1;
    const int kh = blockIdx.z & 1;
    const int kbase = kh * NKC_HALF;
    const int warp_m = (warp >> 2) * 64;
    const int warp_n = (warp & 3) * 32;

    float C[4][4][4];
    float S[4][4][4];
#pragma unroll
    for (int i = 0; i < 4; i++)
#pragma unroll
        for (int j = 0; j < 4; j++)
#pragma unroll
            for (int r = 0; r < 4; r++) { C[i][j][r] = 0.f; S[i][j][r] = 0.f; }

    const int m_lane = lane & 15, hi = lane >> 4;
    const int nb = warp_n >> 3;

    auto load_stage = [&](int kc, uint32_t base) {
        const int k0 = kc * KC;
#pragma unroll
        for (int s = 0; s < 2; s++) {
            const __half* wsrc = g_wh[s];
#pragma unroll
            for (int it = 0; it < 4; it++) {
                int idx = tid + it * 256;
                int m = idx >> 3, c = idx & 7;
                cp16(base + (uint32_t)s * 16384u + (uint32_t)m * 128u + (uint32_t)((c ^ (m & 7)) << 4),
                     wsrc + (size_t)(m0 + m) * KDIM + k0 + c * 8);
            }
#pragma unroll
            for (int it = 0; it < 4; it++) {
                int idx = tid + it * 256;
                int k = idx >> 4, c = idx & 15;
                int kk = k0 + k;
                int cin = kk / 9, rem = kk - cin * 9;
                int ky = rem / 3, kx = rem - ky * 3;
                const __half* src = &g_xh[s][kx][(size_t)(b * CIN + cin) * PLANE + ky * WPAD + p0 + c * 8];
                cp16(base + 32768u + (uint32_t)s * 16384u + (uint32_t)k * 256u + (uint32_t)((c ^ (k & 7)) << 4), src);
            }
        }
        CP_COMMIT();
    };

    load_stage(kbase, sbase);

    for (int lc = 0; lc < NKC_HALF; lc++) {
        CP_WAIT(0);
        __syncthreads();
        if (lc + 1 < NKC_HALF)
            load_stage(kbase + lc + 1, sbase + (uint32_t)((lc + 1) & 1) * BUFB);

        const uint32_t cur = sbase + (uint32_t)(lc & 1) * BUFB;
        const uint32_t sA0 = cur, sA1 = cur + 16384u;
        const uint32_t sB0 = cur + 32768u, sB1 = cur + 49152u;
#pragma unroll
        for (int ks = 0; ks < 4; ks++) {
            uint32_t a0f[4][4], a1f[4][4], b0f[2][4], b1f[2][4];
#pragma unroll
            for (int mi = 0; mi < 4; mi++) {
                int m = warp_m + mi * 16 + m_lane;
                uint32_t off = (uint32_t)m * 128u + (uint32_t)(((ks * 2 + hi) ^ (m_lane & 7)) << 4);
                ldsm4(a0f[mi], sA0 + off);
                ldsm4(a1f[mi], sA1 + off);
            }
#pragma unroll
            for (int ni = 0; ni < 2; ni++) {
                int k = ks * 16 + m_lane;
                uint32_t off = (uint32_t)k * 256u + (uint32_t)(((nb + ni * 2 + hi) ^ (m_lane & 7)) << 4);
                ldsm4t(b0f[ni], sB0 + off);
                ldsm4t(b1f[ni], sB1 + off);
            }
#pragma unroll
            for (int mi = 0; mi < 4; mi++)
#pragma unroll
                for (int g = 0; g < 4; g++) {
                    float* cc = C[mi][g];
                    const uint32_t* pb0 = &b0f[g >> 1][(g & 1) * 2];
                    const uint32_t* pb1 = &b1f[g >> 1][(g & 1) * 2];
                    mma16816(cc, a0f[mi], pb0);
                    mma16816(cc, a0f[mi], pb1);
                    mma16816(cc, a1f[mi], pb0);
                }
        }
        if ((lc & 1) || lc == NKC_HALF - 1) {
#pragma unroll
            for (int mi = 0; mi < 4; mi++)
#pragma unroll
                for (int g = 0; g < 4; g++)
#pragma unroll
                    for (int r = 0; r < 4; r++) {
                        S[mi][g][r] += C[mi][g][r];
                        C[mi][g][r] = 0.f;
                    }
        }
    }

    float* dstp = g_feat2[kh];
#pragma unroll
    for (int mi = 0; mi < 4; mi++)
#pragma unroll
        for (int g = 0; g < 4; g++)
#pragma unroll
            for (int r = 0; r < 4; r++) {
                int pp = p0 + warp_n + g * 8 + (lane & 3) * 2 + (r & 1);
                int y = pp / WPAD, x = pp - y * WPAD;
                if (x < 50 && y < 50) {
                    int m = m0 + warp_m + mi * 16 + (lane >> 2) + 8 * (r >> 1);
                    dstp[((size_t)(b * HW + y * 50 + x) << 9) + m] = S[mi][g][r] * UNSCALE;
                }
            }
}

// ---------------- anchors (also writes pad keys) ----------------
__device__ __forceinline__ void anchor_of(int i, float& ax1, float& ay1, float& ax2, float& ay2) {
    int p = i / 9, a = i - p * 9;
    int y = p / 50, x = p - y * 50;
    int ri = a / 3, si = a - ri * 3;
    const double ratios[3] = {0.5, 1.0, 2.0};
    const double scales[3] = {8.0, 16.0, 32.0};
    double hh = 16.0 * scales[si] * sqrt(ratios[ri]);
    double ww = 16.0 * scales[si] * sqrt(1.0 / ratios[ri]);
    float sx = (float)(x * 16), sy = (float)(y * 16);
    ax1 = sx + (float)(8.0 - ww / 2.0); ay1 = sy + (float)(8.0 - hh / 2.0);
    ax2 = sx + (float)(8.0 + ww / 2.0); ay2 = sy + (float)(8.0 + hh / 2.0);
}
__global__ void anchor_kernel(float* __restrict__ out) {
    int i = blockIdx.x * blockDim.x + threadIdx.x;
    if (i < NANCH) {
        float a1, b1, a2, b2;
        anchor_of(i, a1, b1, a2, b2);
        out[OFF_ANCH + i * 4 + 0] = a1; out[OFF_ANCH + i * 4 + 1] = b1;
        out[OFF_ANCH + i * 4 + 2] = a2; out[OFF_ANCH + i * 4 + 3] = b2;
    } else if (i < PADN) {
#pragma unroll
        for (int b = 0; b < NB; b++)
            g_keys[(size_t)b * PADN + i] = 0xFFFFFFFFFFFFFFFFull;
    }
}

// ---------------- 1x1 heads v2 + fused decode ----------------
__device__ __forceinline__ float dim_to_float(const int* p) {
    int v = *p;
    if (v > 0 && v < 100000) return (float)v;
    return __int_as_float(v);
}

__global__ __launch_bounds__(256)
void heads_kernel(const float* __restrict__ cbias,
                  const float* __restrict__ lw, const float* __restrict__ lb,
                  const float* __restrict__ sw, const float* __restrict__ sb,
                  const int* __restrict__ imh, const int* __restrict__ imw,
                  float* __restrict__ out) {
    extern __shared__ float4 ft4[];
    __shared__ float vals[54][36];
    const int b = blockIdx.y, p0 = blockIdx.x * 32, tid = threadIdx.x;
    const int lane = tid & 31, warp = tid >> 5;

    for (int idx = tid; idx < 32 * 128; idx += 256) {
        int px = idx >> 7, cq = idx & 127;
        float4 v = make_float4(0.f, 0.f, 0.f, 0.f);
        if (p0 + px < HW) {
            size_t o = ((size_t)(b * HW + p0 + px) << 9) + cq * 4;
            float4 vA = *(const float4*)&g_feat2[0][o];
            float4 vB = *(const float4*)&g_feat2[1][o];
            float4 bz = ((const float4*)cbias)[cq];
            v.x = fmaxf(vA.x + vB.x + bz.x, 0.f);
            v.y = fmaxf(vA.y + vB.y + bz.y, 0.f);
            v.z = fmaxf(vA.z + vB.z + bz.z, 0.f);
            v.w = fmaxf(vA.w + vB.w + bz.w, 0.f);
        }
        ft4[cq * 33 + px] = v;
    }
    __syncthreads();

    const int o0 = warp * 7;
    const float4* wrow[7];
    float bias7[7];
#pragma unroll
    for (int oi = 0; oi < 7; oi++) {
        int o = o0 + oi;
        if (o < 36)      { wrow[oi] = (const float4*)(lw + (o << 9));        bias7[oi] = lb[o]; }
        else if (o < 54) { wrow[oi] = (const float4*)(sw + ((o - 36) << 9)); bias7[oi] = sb[o - 36]; }
        else             { wrow[oi] = (const float4*)lw;                     bias7[oi] = 0.f; }
    }

    float acc[7] = {0.f, 0.f, 0.f, 0.f, 0.f, 0.f, 0.f};
#pragma unroll 4
    for (int cq = 0; cq < 128; cq++) {
        float4 f = ft4[cq * 33 + lane];
#pragma unroll
        for (int oi = 0; oi < 7; oi++) {
            float4 wv = __ldg(wrow[oi] + cq);
            acc[oi] += wv.x * f.x + wv.y * f.y + wv.z * f.z + wv.w * f.w;
        }
    }

    const int p = p0 + lane;
#pragma unroll
    for (int oi = 0; oi < 7; oi++) {
        int o = o0 + oi;
        if (o >= 54) break;
        float s = acc[oi] + bias7[oi];
        vals[o][lane] = s;
        if (p < HW) {
            if (o < 36) {
                int a = o >> 2, j = o & 3;
                out[OFF_LOCS + b * (NANCH * 4) + (p * 9 + a) * 4 + j] = s;
            } else {
                int oo = o - 36, a = oo >> 1, j = oo & 1;
                out[OFF_SCORES + b * (NANCH * 2) + (p * 9 + a) * 2 + j] = s;
            }
        }
    }
    __syncthreads();

    const float Wf = dim_to_float(imw), Hf = dim_to_float(imh);
    for (int t = tid; t < 32 * 9; t += 256) {
        int px = t / 9, a = t - px * 9;
        int pp = p0 + px;
        if (pp >= HW) continue;
        int i = pp * 9 + a;
        float ax1, ay1, ax2, ay2;
        anchor_of(i, ax1, ay1, ax2, ay2);
        float l0 = vals[a * 4 + 0][px], l1 = vals[a * 4 + 1][px];
        float l2 = vals[a * 4 + 2][px], l3 = vals[a * 4 + 3][px];
        float aw = ax2 - ax1, ah = ay2 - ay1;
        float cx = l0 * aw + ax1 + 0.5f * aw;
        float cy = l1 * ah + ay1 + 0.5f * ah;
        float ww = expf(l2) * aw, hh = expf(l3) * ah;
        float x1 = fminf(fmaxf(cx - 0.5f * ww, 0.f), Wf);
        float y1 = fminf(fmaxf(cy - 0.5f * hh, 0.f), Hf);
        float x2 = fminf(fmaxf(cx + 0.5f * ww, 0.f), Wf);
        float y2 = fminf(fmaxf(cy + 0.5f * hh, 0.f), Hf);
        bool valid = (x2 - x1 + 1.f >= 16.f) && (y2 - y1 + 1.f >= 16.f);
        float* bx = &g_boxes[((size_t)b * NANCH + i) * 4];
        bx[0] = x1; bx[1] = y1; bx[2] = x2; bx[3] = y2;
        g_valid[b * NANCH + i] = valid ? 1 : 0;
        float s0 = vals[36 + a * 2][px], s1 = vals[37 + a * 2][px];
        float m = fmaxf(s0, s1);
        float e0 = expf(s0 - m), e1 = expf(s1 - m);
        float fg = e1 / (e0 + e1);
        float score = valid ? fg : __int_as_float(0xFF800000);
        unsigned u = __float_as_uint(score);
        unsigned sbits = (u & 0x80000000u) ? ~u : (u | 0x80000000u);
        g_keys[(size_t)b * PADN + i] = ((unsigned long long)(~sbits) << 32) | (unsigned)i;
    }
}

// ---------------- per-chunk bitonic sort (1024 threads) ----------------
__global__ __launch_bounds__(1024)
void sort_kernel() {
    __shared__ unsigned long long sk[CHUNK];
    const int c = blockIdx.x % NCHUNK, b = blockIdx.x / NCHUNK;
    unsigned long long* gk = g_keys + (size_t)b * PADN + c * CHUNK;
    for (int i = threadIdx.x; i < CHUNK; i += 1024) sk[i] = gk[i];
    __syncthreads();
    for (int k = 2; k <= CHUNK; k <<= 1)
        for (int j = k >> 1; j > 0; j >>= 1) {
            for (int t = threadIdx.x; t < CHUNK; t += 1024) {
                int l = t ^ j;
                if (l > t) {
                    bool up = ((t & k) == 0);
                    unsigned long long a = sk[t], bv = sk[l];
                    if ((a > bv) == up) { sk[t] = bv; sk[l] = a; }
                }
            }
            __syncthreads();
        }
    for (int i = threadIdx.x; i < CHUNK; i += 1024) gk[i] = sk[i];
}

// ---------------- co-rank merge -> exact top-3000 ----------------
__global__ void merge_kernel() {
    const int b = blockIdx.y;
    const int t = blockIdx.x * blockDim.x + threadIdx.x;
    if (t >= NCHUNK * NPRE) return;
    const int c = t / NPRE, i = t - c * NPRE;
    const unsigned long long* base = g_keys + (size_t)b * PADN;
    unsigned long long key = __ldg(&base[c * CHUNK + i]);
    if ((unsigned)(key >> 32) == 0xFFFFFFFFu) return;
    int rank = i;
#pragma unroll
    for (int cc = 0; cc < NCHUNK; cc++) {
        if (cc == c) continue;
        const unsigned long long* arr = base + cc * CHUNK;
        int pos = 0;
#pragma unroll
        for (int s = CHUNK / 2; s > 0; s >>= 1)
            if (__ldg(&arr[pos + s - 1]) < key) pos += s;
        rank += pos;
    }
    if (rank < NPRE) {
        int idx = (int)(key & 0xFFFFFFFFull);
        int o = b * NPRE + rank;
        ((float4*)g_sboxes)[o] = *(const float4*)&g_boxes[((size_t)b * NANCH + idx) * 4];
        g_svalid[o] = g_valid[b * NANCH + idx];
    }
}

// ---------------- NMS: suppression bitmatrix (upper-triangle words only) --------
__global__ __launch_bounds__(1024)
void nms_build_kernel() {
    __shared__ float4 bx[NPRE];
    const int b = blockIdx.y, tid = threadIdx.x;
    const int lane = tid & 31, warp = tid >> 5;
    for (int idx = tid; idx < NPRE; idx += 1024)
        bx[idx] = ((const float4*)g_sboxes)[b * NPRE + idx];
    __syncthreads();
    int i = blockIdx.x * 32 + warp;
    if (i >= NPRE) return;
    float4 bi = bx[i];
    float ai = (bi.z - bi.x) * (bi.w - bi.y);
    const int w_start = i >> 5;
    for (int jw = w_start; jw < 94; jw++) {
        int j = jw * 32 + lane;
        bool sup = false;
        if (j < NPRE && j > i) {
            float4 bj = bx[j];
            float iw = fmaxf(fminf(bi.z, bj.z) - fmaxf(bi.x, bj.x), 0.f);
            float ih = fmaxf(fminf(bi.w, bj.w) - fmaxf(bi.y, bj.y), 0.f);
            float inter = iw * ih;
            float aj = (bj.z - bj.x) * (bj.w - bj.y);
            sup = inter / (ai + aj - inter + 1e-9f) > 0.7f;
        }
        unsigned word = __ballot_sync(0xFFFFFFFFu, sup);
        if (lane == 0) g_sup[b][i][jw] = word;
    }
    if (lane < 2) g_sup[b][i][94 + lane] = 0;
}

// ---------------- NMS: single-warp greedy scan (early exit @300 kept) ----------
#define STILE 64
__global__ __launch_bounds__(256)
void nms_scan_kernel(float* __restrict__ out) {
    extern __shared__ unsigned srows[];
    __shared__ unsigned keepw[96];
    __shared__ int done_flag;
    const int b = blockIdx.x, tid = threadIdx.x;
    const int lane = tid & 31, warp = tid >> 5;

    if (tid == 0) done_flag = 0;
    for (int w = tid; w < 96; w += 256) {
        unsigned word = 0;
        for (int q = 0; q < 32; q++) {
            int idx = w * 32 + q;
            if (idx < NPRE && g_svalid[b * NPRE + idx]) word |= (1u << q);
        }
        keepw[w] = word;
    }
    for (int idx = tid; idx < STILE * 24; idx += 256) {
        int i = idx / 24, w4 = idx % 24;
        uint4 v = make_uint4(0, 0, 0, 0);
        if (i < NPRE) v = ((const uint4*)g_sup[b][i])[w4];
        ((uint4*)srows)[idx] = v;
    }
    __syncthreads();

    int cnt_kept = 0;
    const int ntiles = (NPRE + STILE - 1) / STILE;
    for (int t = 0; t < ntiles; t++) {
        if (warp > 0 && t + 1 < ntiles) {
            unsigned* buf = srows + ((t + 1) & 1) * STILE * 96;
            for (int idx = tid - 32; idx < STILE * 24; idx += 224) {
                int i = (t + 1) * STILE + idx / 24, w4 = idx % 24;
                uint4 v = make_uint4(0, 0, 0, 0);
                if (i < NPRE) v = ((const uint4*)g_sup[b][i])[w4];
                ((uint4*)buf)[idx] = v;
            }
        }
        if (warp == 0) {
            const unsigned* buf = srows + (t & 1) * STILE * 96;
            unsigned wcur = 0;
            for (int ii = 0; ii < STILE; ii++) {
                int i = t * STILE + ii;
                if (i >= NPRE) break;
                int cw = i >> 5, bit = i & 31;
                if (bit == 0) { __syncwarp(); wcur = keepw[cw]; }
                if ((wcur >> bit) & 1) {
                    const unsigned* row = buf + ii * 96;
                    wcur &= ~row[cw];
                    keepw[lane]      &= ~row[lane];
                    keepw[lane + 32] &= ~row[lane + 32];
                    keepw[lane + 64] &= ~row[lane + 64];
                    if (++cnt_kept >= NPOST) break;
                }
            }
            __syncwarp();
            if (lane == 0 && cnt_kept >= NPOST) done_flag = 1;
        }
        __syncthreads();
        if (done_flag) break;
    }

    for (int q = tid; q < NPOST * 4; q += 256) out[OFF_ROIS + b * (NPOST * 4) + q] = 0.f;
    for (int q = tid; q < NPOST; q += 256) out[OFF_RIDX + b * NPOST + q] = (float)b;
    __syncthreads();

    if (warp == 0) {
        int cnt = 0;
        for (int w0 = 0; w0 < 94; w0++) {
            unsigned flags = keepw[w0];
            int j = w0 * 32 + lane;
            bool f = (flags >> lane) & 1;
            int pos = cnt + __popc(flags & ((1u << lane) - 1u));
            if (f && pos < NPOST && j < NPRE) {
                float4 bb = ((const float4*)g_sboxes)[b * NPRE + j];
                float* o = out + OFF_ROIS + b * (NPOST * 4) + pos * 4;
                o[0] = bb.x; o[1] = bb.y; o[2] = bb.z; o[3] = bb.w;
            }
            cnt += __popc(flags);
            if (cnt >= NPOST) break;
        }
    }
}

// ---------------- launcher ----------------
extern "C" void kernel_launch(void* const* d_in, const int* in_sizes, int n_in,
                              void* d_out, int out_size) {
    const float* x  = (const float*)d_in[0];
    const float* w1 = (const float*)d_in[1];
    const float* b1 = (const float*)d_in[2];
    const float* lw = (const float*)d_in[3];
    const float* lb = (const float*)d_in[4];
    const float* sw = (const float*)d_in[5];
    const float* sb = (const float*)d_in[6];
    const int* ih   = (const int*)d_in[7];
    const int* iw   = (const int*)d_in[8];
    float* out = (float*)d_out;

    cudaFuncSetAttribute(conv_mma_kernel, cudaFuncAttributeMaxDynamicSharedMemorySize, CONV_SMEM);
    cudaFuncSetAttribute(heads_kernel, cudaFuncAttributeMaxDynamicSharedMemorySize, HEADS_SMEM);
    cudaFuncSetAttribute(nms_scan_kernel, cudaFuncAttributeMaxDynamicSharedMemorySize, 2 * STILE * 96 * 4);

    anchor_kernel<<<(PADN + 255) / 256, 256>>>(out);                        // launch 0
    split_x_kernel<<<NB * CIN, 256>>>(x);                                   // launch 1
    split_w_kernel<<<(COUT * KDIM / 4 + 255) / 256, 256>>>(w1);             // launch 2
    conv_mma_kernel<<<dim3(NTILES_N, 4, NB * 2), 256, CONV_SMEM>>>();       // launch 3 (profiled)
    heads_kernel<<<dim3((HW + 31) / 32, NB), 256, HEADS_SMEM>>>(b1, lw, lb, sw, sb, ih, iw, out);
    sort_kernel<<<NB * NCHUNK, 1024>>>();
    merge_kernel<<<dim3((NCHUNK * NPRE + 255) / 256, NB), 256>>>();
    nms_build_kernel<<<dim3((NPRE + 31) / 32, NB), 1024>>>();
    nms_scan_kernel<<<NB, 256, 2 * STILE * 96 * 4>>>(out);
}